// round 12
// baseline (speedup 1.0000x reference)
#include <cuda_runtime.h>
#include <cstdint>

// GlobalMixer: y[b,h,o,g] = sum_i W[h,o,i] * x[b,h,i,g]
//   x: (B=512, H=512, SEQ=256) fp32, SEQ elem (i,g) at i*16+g
//   W: (H=512, 16, 16) fp32
//
// R12: R9 (82.0us best) + 2-tile persistence. Unlike R4 (which failed),
// this keeps the hoisted-load structure and a fine 4096-CTA grid: tile 2
// skips the W/STS/BAR startup, and __restrict__ lets ptxas hoist tile-2's
// 16 independent LDGs into tile-1's store drain -> halves the exposed
// CTA-startup events R8 proved costly. Compute shape unchanged (g-quad,
// unsplatted smem W, packed f32x2 FMA, streaming .cs).

#define HIDDEN 512
#define BATCH  512
#define B_PER_TILE 32
#define TILES 2
#define THREADS 128

__device__ __forceinline__ unsigned long long fma2(unsigned long long a,
                                                   unsigned long long b,
                                                   unsigned long long c) {
    unsigned long long d;
    asm("fma.rn.f32x2 %0, %1, %2, %3;" : "=l"(d) : "l"(a), "l"(b), "l"(c));
    return d;
}

__device__ __forceinline__ unsigned long long splat2(float w) {
    unsigned long long d;
    asm("mov.b64 %0, {%1, %1};" : "=l"(d) : "f"(w));
    return d;
}

__global__ __launch_bounds__(THREADS, 4)
void global_mixer_kernel(const float* __restrict__ x,
                         const float* __restrict__ W,
                         float* __restrict__ y) {
    __shared__ float ws[256];               // W[h] plain fp32, 1 KB

    const int h  = blockIdx.x;              // 0..511
    const int t  = threadIdx.x;             // 0..127

    const int b_local = t >> 2;   // 0..31
    const int gq      = t & 3;    // g-quad -> g = 4*gq .. 4*gq+3

    const int b_first = blockIdx.y * (B_PER_TILE * TILES) + b_local;
    const size_t base0 =
        ((size_t)b_first * HIDDEN + h) * 256 + gq * 4;
    // Tile stride in elements: B_PER_TILE * HIDDEN * 256
    const size_t tile_stride = (size_t)B_PER_TILE * HIDDEN * 256 / 4; // in ulonglong2... computed below

    // Tile 0 DRAM loads FIRST: overlap with W L2-load + STS + BAR
    const ulonglong2* __restrict__ xp0 =
        reinterpret_cast<const ulonglong2*>(x + base0);
    ulonglong2 xv[16];
#pragma unroll
    for (int i = 0; i < 16; i++) xv[i] = __ldcs(xp0 + (size_t)i * 4);

    ws[t]       = W[h * 256 + t];
    ws[t + 128] = W[h * 256 + t + 128];
    __syncthreads();

#pragma unroll
    for (int tile = 0; tile < TILES; tile++) {
        const size_t base = base0 + (size_t)tile * B_PER_TILE * HIDDEN * 256;
        ulonglong2* __restrict__ yp =
            reinterpret_cast<ulonglong2*>(y + base);

#pragma unroll
        for (int o = 0; o < 16; o++) {
            unsigned long long alo = 0ull, ahi = 0ull;
            const float4* __restrict__ wrow =
                reinterpret_cast<const float4*>(&ws[o * 16]);
#pragma unroll
            for (int i4 = 0; i4 < 4; i4++) {
                float4 w = wrow[i4];        // LDS.128: 4 distinct W values
                unsigned long long w0 = splat2(w.x);
                unsigned long long w1 = splat2(w.y);
                unsigned long long w2 = splat2(w.z);
                unsigned long long w3 = splat2(w.w);
                alo = fma2(xv[4 * i4 + 0].x, w0, alo);
                ahi = fma2(xv[4 * i4 + 0].y, w0, ahi);
                alo = fma2(xv[4 * i4 + 1].x, w1, alo);
                ahi = fma2(xv[4 * i4 + 1].y, w1, ahi);
                alo = fma2(xv[4 * i4 + 2].x, w2, alo);
                ahi = fma2(xv[4 * i4 + 2].y, w2, ahi);
                alo = fma2(xv[4 * i4 + 3].x, w3, alo);
                ahi = fma2(xv[4 * i4 + 3].y, w3, ahi);
            }
            ulonglong2 out; out.x = alo; out.y = ahi;
            __stcs(yp + (size_t)o * 4, out);    // STG.128 streaming
        }

        // Load next tile's x right after this tile's FMAs; independent of
        // the STGs above (restrict-proven), so ptxas can interleave them
        // with the store drain. Skipped on the last tile.
        if (tile + 1 < TILES) {
            const size_t nbase =
                base0 + (size_t)(tile + 1) * B_PER_TILE * HIDDEN * 256;
            const ulonglong2* __restrict__ xpn =
                reinterpret_cast<const ulonglong2*>(x + nbase);
#pragma unroll
            for (int i = 0; i < 16; i++) xv[i] = __ldcs(xpn + (size_t)i * 4);
        }
    }
}

extern "C" void kernel_launch(void* const* d_in, const int* in_sizes, int n_in,
                              void* d_out, int out_size) {
    const float* x = (const float*)d_in[0];   // 512*512*256 fp32
    const float* W = (const float*)d_in[1];   // 512*16*16 fp32
    float* y = (float*)d_out;

    dim3 grid(HIDDEN, BATCH / (B_PER_TILE * TILES));   // (512, 8)
    global_mixer_kernel<<<grid, THREADS>>>(x, W, y);
}

// round 13
// speedup vs baseline: 2.5632x; 2.5632x over previous
#include <cuda_runtime.h>
#include <cstdint>

// GlobalMixer: y[b,h,o,g] = sum_i W[h,o,i] * x[b,h,i,g]
//   x: (B=512, H=512, SEQ=256) fp32, SEQ elem (i,g) at i*16+g
//   W: (H=512, 16, 16) fp32
//
// R13 = R9 verbatim (best: 82.0us harness, 77.0us in-kernel, ~7.0 TB/s
// effective = 88% of HBM spec on a 1:1 R/W stream). Final configuration
// after the full lever ledger:
//   validated: g-quad L1 shape (R2), unsplatted smem W (R3), hoisted
//              front-batched x loads (R8: -2.1us), 128-thread/4-CTA phase
//              granularity (R9: -0.4us)
//   falsified: occupancy (R4, R10), demand smoothness (R6), DRAM address
//              density (R7), multi-tile persistence (R4, R12: reg-spill
//              blowup, 2.2x traffic)
// Remaining gap to the 67us spec floor is HBM read/write turnaround,
// unreachable from the SM side.

#define HIDDEN 512
#define BATCH  512
#define B_PER_BLOCK 32
#define THREADS 128

__device__ __forceinline__ unsigned long long fma2(unsigned long long a,
                                                   unsigned long long b,
                                                   unsigned long long c) {
    unsigned long long d;
    asm("fma.rn.f32x2 %0, %1, %2, %3;" : "=l"(d) : "l"(a), "l"(b), "l"(c));
    return d;
}

__device__ __forceinline__ unsigned long long splat2(float w) {
    unsigned long long d;
    asm("mov.b64 %0, {%1, %1};" : "=l"(d) : "f"(w));
    return d;
}

__global__ __launch_bounds__(THREADS, 4)
void global_mixer_kernel(const float* __restrict__ x,
                         const float* __restrict__ W,
                         float* __restrict__ y) {
    __shared__ float ws[256];               // W[h] plain fp32, 1 KB

    const int h  = blockIdx.x;              // 0..511
    const int b0 = blockIdx.y * B_PER_BLOCK;
    const int t  = threadIdx.x;             // 0..127

    const int b_local = t >> 2;   // 0..31
    const int gq      = t & 3;    // g-quad -> g = 4*gq .. 4*gq+3

    const size_t base = ((size_t)(b0 + b_local) * HIDDEN + h) * 256 + gq * 4;
    const ulonglong2* __restrict__ xp =
        reinterpret_cast<const ulonglong2*>(x + base);
    ulonglong2* __restrict__ yp =
        reinterpret_cast<ulonglong2*>(y + base);

    // DRAM loads FIRST: overlap their latency with the W L2-load + STS + BAR
    ulonglong2 xv[16];
#pragma unroll
    for (int i = 0; i < 16; i++) xv[i] = __ldcs(xp + (size_t)i * 4);

    // W stage: 128 threads x 2 elements (L2-resident)
    ws[t]       = W[h * 256 + t];
    ws[t + 128] = W[h * 256 + t + 128];
    __syncthreads();

#pragma unroll
    for (int o = 0; o < 16; o++) {
        unsigned long long alo = 0ull, ahi = 0ull;
        const float4* __restrict__ wrow =
            reinterpret_cast<const float4*>(&ws[o * 16]);
#pragma unroll
        for (int i4 = 0; i4 < 4; i4++) {
            float4 w = wrow[i4];            // LDS.128: 4 distinct W values
            unsigned long long w0 = splat2(w.x);
            unsigned long long w1 = splat2(w.y);
            unsigned long long w2 = splat2(w.z);
            unsigned long long w3 = splat2(w.w);
            alo = fma2(xv[4 * i4 + 0].x, w0, alo);
            ahi = fma2(xv[4 * i4 + 0].y, w0, ahi);
            alo = fma2(xv[4 * i4 + 1].x, w1, alo);
            ahi = fma2(xv[4 * i4 + 1].y, w1, ahi);
            alo = fma2(xv[4 * i4 + 2].x, w2, alo);
            ahi = fma2(xv[4 * i4 + 2].y, w2, ahi);
            alo = fma2(xv[4 * i4 + 3].x, w3, alo);
            ahi = fma2(xv[4 * i4 + 3].y, w3, ahi);
        }
        ulonglong2 out; out.x = alo; out.y = ahi;
        __stcs(yp + (size_t)o * 4, out);    // STG.128 streaming, coalesced
    }
}

extern "C" void kernel_launch(void* const* d_in, const int* in_sizes, int n_in,
                              void* d_out, int out_size) {
    const float* x = (const float*)d_in[0];   // 512*512*256 fp32
    const float* W = (const float*)d_in[1];   // 512*16*16 fp32
    float* y = (float*)d_out;

    dim3 grid(HIDDEN, BATCH / B_PER_BLOCK);   // (512, 16)
    global_mixer_kernel<<<grid, THREADS>>>(x, W, y);
}